// round 5
// baseline (speedup 1.0000x reference)
#include <cuda_runtime.h>
#include <cstdint>

typedef unsigned long long u64;

// ---- packed f32x2 helpers (Blackwell packed-fp32 path; PTX-only) ----
__device__ __forceinline__ u64 pk2(float lo, float hi) {
    u64 r; asm("mov.b64 %0, {%1, %2};" : "=l"(r) : "f"(lo), "f"(hi)); return r;
}
__device__ __forceinline__ void upk2(u64 v, float& lo, float& hi) {
    asm("mov.b64 {%0, %1}, %2;" : "=f"(lo), "=f"(hi) : "l"(v));
}
__device__ __forceinline__ u64 mul2(u64 a, u64 b) {
    u64 r; asm("mul.rn.f32x2 %0, %1, %2;" : "=l"(r) : "l"(a), "l"(b)); return r;
}
__device__ __forceinline__ u64 add2(u64 a, u64 b) {
    u64 r; asm("add.rn.f32x2 %0, %1, %2;" : "=l"(r) : "l"(a), "l"(b)); return r;
}
__device__ __forceinline__ u64 fma2(u64 a, u64 b, u64 c) {
    u64 r; asm("fma.rn.f32x2 %0, %1, %2, %3;" : "=l"(r) : "l"(a), "l"(b), "l"(c)); return r;
}

// SIR RK4, beta-scaled + h/2-scaled state: a=(h/2)*beta*S, v=beta*I.
// 21 packed ops/substep, 4 substeps per saved step. Each thread carries TWO
// independent packed states (4 batch elements) so the per-substep RAW chain
// of one state is covered by issuing the other state's instructions (the
// Round-4 profile showed the single-chain version latency-bound: fma 30%,
// issue 24%). R recovered from the invariant R = 1 - S - I.
__global__ void __launch_bounds__(32) sir_rk4(const float* __restrict__ params,
                                              float* __restrict__ out, int n)
{
    const int gid = blockIdx.x * 32 + threadIdx.x;
    const int b0 = gid * 4;
    if (b0 + 3 >= n) return;

    float4 pp[4];
    #pragma unroll
    for (int e = 0; e < 4; e++)
        pp[e] = reinterpret_cast<const float4*>(params)[b0 + e];

    const float hf  = (100.0f / 199.0f) / 4.0f;
    const float h2f = 0.5f * hf;
    const float h6f = hf / 6.0f;

    // shared packed constants
    const u64 NH2  = pk2(-h2f, -h2f);
    const u64 NH   = pk2(-hf,  -hf);
    const u64 NH6  = pk2(-h6f, -h6f);
    const u64 TWO  = pk2(2.0f, 2.0f);
    const u64 THRD = pk2(1.0f/3.0f, 1.0f/3.0f);
    const u64 ONE  = pk2(1.0f, 1.0f);
    const u64 N1   = pk2(-1.0f, -1.0f);

    // per-state (element-pair) constants and state
    u64 C1[2], NH2G[2], NHG[2], NH6G[2], IB2[2], IB[2], A[2], V[2];
    #pragma unroll
    for (int st = 0; st < 2; st++) {
        const float4 pa = pp[2*st], pb = pp[2*st + 1];
        const float bA = fmaxf(pa.x, 1e-20f);
        const float bB = fmaxf(pb.x, 1e-20f);
        const float gA = pa.y, gB = pb.y;
        C1[st]   = pk2(1.0f - h2f*gA, 1.0f - h2f*gB);
        NH2G[st] = pk2(-h2f*gA, -h2f*gB);
        NHG[st]  = pk2(-hf*gA,  -hf*gB);
        NH6G[st] = pk2(-h6f*gA, -h6f*gB);
        IB2[st]  = pk2(1.0f/(h2f*bA), 1.0f/(h2f*bB));
        IB[st]   = pk2(1.0f/bA, 1.0f/bB);
        A[st]    = pk2(h2f * bA * pa.z, h2f * bB * pb.z);
        V[st]    = pk2(bA * pa.w, bB * pb.w);
    }

    float4* optr[4];
    #pragma unroll
    for (int e = 0; e < 4; e++)
        optr[e] = reinterpret_cast<float4*>(out + (size_t)(b0 + e) * 600);

    // Staged results: [step-in-chunk][element] floats.
    float fS[4][4], fI[4][4], fR[4][4];

    // One fused substep for BOTH states: 42 packed ops, two independent
    // chains interleaved line-by-line so ptxas keeps issue slots full.
    auto substep2 = [&]() {
        u64 p1x = mul2(A[0], V[0]);            u64 p1y = mul2(A[1], V[1]);
        u64 a2x = fma2(NH2, p1x, A[0]);        u64 a2y = fma2(NH2, p1y, A[1]);
        u64 v2x = fma2(C1[0], V[0], p1x);      u64 v2y = fma2(C1[1], V[1], p1y);
        u64 p2x = mul2(a2x, v2x);              u64 p2y = mul2(a2y, v2y);
        u64 a3x = fma2(NH2, p2x, A[0]);        u64 a3y = fma2(NH2, p2y, A[1]);
        u64 t3x = fma2(NH2G[0], v2x, V[0]);    u64 t3y = fma2(NH2G[1], v2y, V[1]);
        u64 v3x = add2(t3x, p2x);              u64 v3y = add2(t3y, p2y);
        u64 p3x = mul2(a3x, v3x);              u64 p3y = mul2(a3y, v3y);
        u64 a4x = fma2(NH, p3x, A[0]);         u64 a4y = fma2(NH, p3y, A[1]);
        u64 t4x = fma2(NHG[0], v3x, V[0]);     u64 t4y = fma2(NHG[1], v3y, V[1]);
        u64 v4x = fma2(TWO, p3x, t4x);         u64 v4y = fma2(TWO, p3y, t4y);
        u64 p4x = mul2(a4x, v4x);              u64 p4y = mul2(a4y, v4y);
        u64 ux  = add2(p1x, p4x);              u64 uy  = add2(p1y, p4y);
        u64 tx  = add2(p2x, p3x);              u64 ty  = add2(p2y, p3y);
        u64 sx  = fma2(TWO, tx, ux);           u64 sy  = fma2(TWO, ty, uy);
        A[0] = fma2(NH6, sx, A[0]);            A[1] = fma2(NH6, sy, A[1]);
        u64 uvx = add2(V[0], v4x);             u64 uvy = add2(V[1], v4y);
        u64 tvx = add2(v2x, v3x);              u64 tvy = add2(v2y, v3y);
        u64 lvx = fma2(TWO, tvx, uvx);         u64 lvy = fma2(TWO, tvy, uvy);
        u64 nvx = fma2(THRD, sx, V[0]);        u64 nvy = fma2(THRD, sy, V[1]);
        V[0] = fma2(NH6G[0], lvx, nvx);        V[1] = fma2(NH6G[1], lvy, nvy);
    };

    auto step = [&]() {
        #pragma unroll
        for (int s = 0; s < 4; s++) substep2();
    };

    // Convert current state -> (S, I, R) floats into stage slot j.
    auto record = [&](int j) {
        #pragma unroll
        for (int st = 0; st < 2; st++) {
            u64 s = mul2(A[st], IB2[st]);
            u64 i = mul2(V[st], IB[st]);
            u64 t = add2(s, i);
            u64 r = fma2(N1, t, ONE);          // R = 1 - (S + I)
            upk2(s, fS[j][2*st], fS[j][2*st+1]);
            upk2(i, fI[j][2*st], fI[j][2*st+1]);
            upk2(r, fR[j][2*st], fR[j][2*st+1]);
        }
    };

    // Store one 16-byte piece (j in 0..2) of chunk c's staged 48B row,
    // for all four elements. Piece layout over (S,I,R) x 4 steps:
    //   piece0 = (S0,I0,R0,S1), piece1 = (I1,R1,S2,I2), piece2 = (R2,S3,I3,R3)
    auto store_piece = [&](int c, int j) {
        #pragma unroll
        for (int e = 0; e < 4; e++) {
            float4* p = optr[e] + c * 3;
            if (j == 0)
                p[0] = make_float4(fS[0][e], fI[0][e], fR[0][e], fS[1][e]);
            else if (j == 1)
                p[1] = make_float4(fI[1][e], fR[1][e], fS[2][e], fI[2][e]);
            else
                p[2] = make_float4(fR[2][e], fS[3][e], fI[3][e], fR[3][e]);
        }
    };

    // Chunk 0: exact y0 (matching reference ordering) + 3 integrated steps.
    #pragma unroll
    for (int e = 0; e < 4; e++) {
        fS[0][e] = pp[e].z;
        fI[0][e] = pp[e].w;
        fR[0][e] = (1.0f - pp[e].z) - pp[e].w;
    }
    #pragma unroll
    for (int j = 1; j < 4; j++) { step(); record(j); }

    // Chunks 1..49: store previous chunk's pieces interleaved with compute.
    #pragma unroll 1
    for (int c = 1; c < 50; c++) {
        #pragma unroll
        for (int j = 0; j < 4; j++) {
            if (j < 3) store_piece(c - 1, j);
            step();
            record(j);
        }
    }

    // Final flush for chunk 49.
    store_piece(49, 0);
    store_piece(49, 1);
    store_piece(49, 2);
}

extern "C" void kernel_launch(void* const* d_in, const int* in_sizes, int n_in,
                              void* d_out, int out_size)
{
    const float* params = (const float*)d_in[0];
    float* out = (float*)d_out;
    const int n = in_sizes[0] / 4;        // batch elements (65536)
    const int nthreads = (n + 3) / 4;     // 4 elements per thread (2 packed states)
    const int blocks = (nthreads + 31) / 32;
    sir_rk4<<<blocks, 32>>>(params, out, n);
}

// round 7
// speedup vs baseline: 1.1838x; 1.1838x over previous
#include <cuda_runtime.h>
#include <cstdint>

// SIR RK4, scalar fp32, ONE batch element per thread (65536 threads, 2048
// warps -> ~14 warps/SM: scalar FFMA lat=4 fully covered by warp parallelism,
// unlike the packed-f32x2 path whose measured dependent latency ~13-15 cyc
// left Rounds 4/5 latency-bound at fma pipe 25-30%).
// State: a = (h/2)*beta*S, v = beta*I  ->  21 FFMA-class ops/substep, with
// the h-derived coefficients as compile-time immediates (FFMA-imm rt=1).
// 4 substeps per saved step; R recovered from the invariant R = 1 - S - I.
__global__ void __launch_bounds__(64) sir_rk4(const float* __restrict__ params,
                                              float* __restrict__ out, int n)
{
    const int gid = blockIdx.x * 64 + threadIdx.x;
    if (gid >= n) return;

    const float4 p = reinterpret_cast<const float4*>(params)[gid];

    constexpr float H  = (100.0f / 199.0f) / 4.0f;  // substep size
    constexpr float H2 = 0.5f * H;
    constexpr float H6 = H / 6.0f;

    const float beta = fmaxf(p.x, 1e-20f);
    const float g    = p.y;

    // gamma/beta-dependent coefficients (registers)
    const float c1   = 1.0f - H2 * g;
    const float nh2g = -H2 * g;
    const float nhg  = -H  * g;
    const float nh6g = -H6 * g;
    const float ib   = 1.0f / beta;
    const float ib2  = 1.0f / (H2 * beta);

    float a = H2 * beta * p.z;     // (h/2)*beta*S
    float v = beta * p.w;          // beta*I

    float4* optr = reinterpret_cast<float4*>(out + (size_t)gid * 600);

    // Staged results for 4 steps: 12 floats = 3 x float4.
    float fS[4], fI[4], fR[4];

    auto substep = [&]() {
        float p1 = a * v;
        float a2 = fmaf(-H2, p1, a);          // imm
        float v2 = fmaf(c1, v, p1);
        float p2 = a2 * v2;
        float a3 = fmaf(-H2, p2, a);          // imm
        float t3 = fmaf(nh2g, v2, v);
        float v3 = t3 + p2;
        float p3 = a3 * v3;
        float a4 = fmaf(-H, p3, a);           // imm
        float t4 = fmaf(nhg, v3, v);
        float v4 = fmaf(2.0f, p3, t4);        // imm
        float p4 = a4 * v4;
        float u  = p1 + p4;
        float t  = p2 + p3;
        float s  = fmaf(2.0f, t, u);          // imm
        a = fmaf(-H6, s, a);                  // imm
        float uv = v + v4;
        float tv = v2 + v3;
        float lv = fmaf(2.0f, tv, uv);        // imm
        float nv = fmaf(1.0f / 3.0f, s, v);   // imm
        v = fmaf(nh6g, lv, nv);
    };

    auto step = [&]() {
        #pragma unroll
        for (int s = 0; s < 4; s++) substep();
    };

    auto record = [&](int j) {
        float S = a * ib2;
        float I = v * ib;
        fS[j] = S;
        fI[j] = I;
        fR[j] = 1.0f - (S + I);               // RK4-preserved invariant
    };

    auto flush = [&](int c) {
        float4* q = optr + c * 3;
        q[0] = make_float4(fS[0], fI[0], fR[0], fS[1]);
        q[1] = make_float4(fI[1], fR[1], fS[2], fI[2]);
        q[2] = make_float4(fR[2], fS[3], fI[3], fR[3]);
    };

    // Chunk 0: exact y0 (matching reference) + 3 integrated steps.
    fS[0] = p.z;
    fI[0] = p.w;
    fR[0] = (1.0f - p.z) - p.w;
    #pragma unroll
    for (int j = 1; j < 4; j++) { step(); record(j); }
    flush(0);

    // Chunks 1..49: 4 integrated steps each (3 + 49*4 = 199 steps).
    #pragma unroll 1
    for (int c = 1; c < 50; c++) {
        #pragma unroll
        for (int j = 0; j < 4; j++) { step(); record(j); }
        flush(c);
    }
}

extern "C" void kernel_launch(void* const* d_in, const int* in_sizes, int n_in,
                              void* d_out, int out_size)
{
    const float* params = (const float*)d_in[0];
    float* out = (float*)d_out;
    const int n = in_sizes[0] / 4;          // batch elements (65536)
    const int blocks = (n + 63) / 64;       // one element per thread
    sir_rk4<<<blocks, 64>>>(params, out, n);
}